// round 11
// baseline (speedup 1.0000x reference)
#include <cuda_runtime.h>
#include <cuda_fp16.h>
#include <cstdint>

#define BATCH      256
#define INPUT_DIM  4096
#define SOMA       2048
#define BRANCH     16
#define NUM_DEND   (SOMA * BRANCH)   // 32768
#define SAMPLE     32
#define NEG        0.1f

#define BT         8                 // batches per block (4x half2 = 16B per x element)
#define NBG        (BATCH / BT)      // 32 batch groups
#define DT         512
#define NTHREADS   512

#define PREP_THREADS 256
#define XB   ((NBG * 2 * INPUT_DIM) / PREP_THREADS)   // 1024 blocks for x prep
#define PB   (NUM_DEND / PREP_THREADS)                // 128 blocks for pack prep

#define XS_BYTES (INPUT_DIM * 16)    // 64 KB

// Scratch (allocation-free rule: __device__ globals)
// pk word layout: [15:0] = w (fp16 bits), [31:16] = ix<<4 (byte offset)
__device__ uint4  g_pk[(SAMPLE/4) * NUM_DEND];     // [s4][d], 4 MB
__device__ uint4  g_xprep[NBG * INPUT_DIM];        // [bg][i]: 8 batches as 4x half2, 2 MB

__device__ __forceinline__ uint32_t smem_u32(const void* p) {
    uint32_t a;
    asm("{ .reg .u64 t; cvta.to.shared.u64 t, %1; cvt.u32.u64 %0, t; }" : "=r"(a) : "l"(p));
    return a;
}

// ---- fused pre-pass: x packing (blocks < XB) + idx/w pack-sort (blocks >= XB) ----
__global__ void prep_fused(const float* __restrict__ x,
                           const int*   __restrict__ idx,
                           const float* __restrict__ sw)
{
    asm volatile("griddepcontrol.launch_dependents;");

    __shared__ unsigned buf[SAMPLE * PREP_THREADS];  // 32 KB (used by pack part)
    const int tid = threadIdx.x;

    if (blockIdx.x < XB) {
        // ---- pack x into batch-interleaved fp16 ----
        int t  = blockIdx.x * PREP_THREADS + tid;     // 0 .. NBG*2*INPUT_DIM-1
        int bg = t / (2 * INPUT_DIM);
        int r  = t - bg * 2 * INPUT_DIM;
        int h  = r / INPUT_DIM;
        int i  = r - h * INPUT_DIM;

        const float* xr = x + ((size_t)bg * BT + h * 4) * INPUT_DIM + i;
        __half2 a = __floats2half2_rn(xr[0],             xr[INPUT_DIM]);
        __half2 b = __floats2half2_rn(xr[2 * INPUT_DIM], xr[3 * INPUT_DIM]);
        uint2 v;
        v.x = *reinterpret_cast<unsigned*>(&a);
        v.y = *reinterpret_cast<unsigned*>(&b);
        reinterpret_cast<uint2*>(g_xprep)[(size_t)(bg * INPUT_DIM + i) * 2 + h] = v;
        return;
    }

    // ---- pack {off16 = ix<<4, w fp16} with FIXED-SLOT bank-class schedule ----
    const int d = (blockIdx.x - XB) * PREP_THREADS + tid;

    const int4*   ir = reinterpret_cast<const int4*>(idx) + (size_t)d * (SAMPLE/4);
    const float4* wr = reinterpret_cast<const float4*>(sw) + (size_t)d * (SAMPLE/4);

    unsigned pkv[SAMPLE];
    #pragma unroll
    for (int s4 = 0; s4 < SAMPLE/4; ++s4) {
        const int4   i4 = ir[s4];
        const float4 w4 = wr[s4];
        #pragma unroll
        for (int q = 0; q < 4; ++q) {
            const int   ix = (q == 0) ? i4.x : (q == 1) ? i4.y : (q == 2) ? i4.z : i4.w;
            const float w  = (q == 0) ? w4.x : (q == 1) ? w4.y : (q == 2) ? w4.z : w4.w;
            pkv[4*s4 + q] = (unsigned)__half_as_ushort(__float2half_rn(w))
                          | ((unsigned)ix << 20);            // (ix<<4) in high 16
        }
    }

    // Pass A: class c (= ix&7 = bits [22:20]) owns slots 4c..4c+3
    unsigned long long fill = 0ull;
    unsigned unplaced = 0u;
    #pragma unroll
    for (int e = 0; e < SAMPLE; ++e) {
        const int c = (int)((pkv[e] >> 20) & 7u);
        const int p = (int)((fill >> (8 * c)) & 0xff);
        if (p < 4) {
            fill += 1ull << (8 * c);
            buf[(4 * c + p) * PREP_THREADS + tid] = pkv[e];
        } else {
            unplaced |= 1u << e;
        }
    }
    // Pass B: overflow fills deficit slots (static pkv indices)
    {
        int cslot = 0;
        #pragma unroll
        for (int e = 0; e < SAMPLE; ++e) {
            if ((unplaced >> e) & 1u) {
                while (((fill >> (8 * cslot)) & 0xffull) >= 4) ++cslot;
                const int p = (int)((fill >> (8 * cslot)) & 0xff);
                fill += 1ull << (8 * cslot);
                buf[(4 * cslot + p) * PREP_THREADS + tid] = pkv[e];
            }
        }
    }

    // Output with per-lane rotation so quarter-warp classes are staggered
    const int rot = 4 * (d & 7);
    #pragma unroll
    for (int s4 = 0; s4 < SAMPLE/4; ++s4) {
        uint4 p;
        p.x = buf[(((4*s4 + 0) + rot) & 31) * PREP_THREADS + tid];
        p.y = buf[(((4*s4 + 1) + rot) & 31) * PREP_THREADS + tid];
        p.z = buf[(((4*s4 + 2) + rot) & 31) * PREP_THREADS + tid];
        p.w = buf[(((4*s4 + 3) + rot) & 31) * PREP_THREADS + tid];
        g_pk[s4 * NUM_DEND + d] = p;
    }
}

// ---- main kernel ----
__global__ __launch_bounds__(NTHREADS, 2)
void dend_kernel(const float* __restrict__ sb,
                 const float* __restrict__ cw,
                 const float* __restrict__ somab,
                 float* __restrict__ soma_out,
                 float* __restrict__ dend_out)
{
    extern __shared__ uint4 xs[];   // [INPUT_DIM] = 64 KB
    __shared__ __align__(8) uint64_t mbar;

    const int bg  = blockIdx.y;
    const int b0  = bg * BT;
    const int d0  = blockIdx.x * DT;
    const int tid = threadIdx.x;

    const uint32_t mbar_a = smem_u32(&mbar);
    const uint32_t xs_a   = smem_u32(xs);

    if (tid == 0) {
        asm volatile("mbarrier.init.shared::cta.b64 [%0], 1;" :: "r"(mbar_a) : "memory");
    }
    __syncthreads();

    // PDL: block until prep_fused fully completes (memory visible)
    asm volatile("griddepcontrol.wait;" ::: "memory");

    if (tid == 0) {
        asm volatile("mbarrier.arrive.expect_tx.shared::cta.b64 _, [%0], %1;"
                     :: "r"(mbar_a), "r"((unsigned)XS_BYTES) : "memory");
        asm volatile("cp.async.bulk.shared::cta.global.mbarrier::complete_tx::bytes "
                     "[%0], [%1], %2, [%3];"
                     :: "r"(xs_a), "l"(g_xprep + (size_t)bg * INPUT_DIM),
                        "r"((unsigned)XS_BYTES), "r"(mbar_a) : "memory");
    }

    const int d = d0 + tid;

    // Prefetch first pk + scalars while TMA fills smem
    const uint4 pk0  = g_pk[d];
    const float bias = sb[d];
    const float cwv  = cw[d];   // cable_weights flattened [soma][branch] == index d

    // Wait for bulk copy completion (phase 0)
    {
        unsigned done;
        asm volatile(
            "{\n\t.reg .pred p;\n\t"
            "mbarrier.try_wait.parity.acquire.cta.shared::cta.b64 p, [%1], 0;\n\t"
            "selp.b32 %0, 1, 0, p;\n\t}"
            : "=r"(done) : "r"(mbar_a) : "memory");
        while (!done) {
            asm volatile(
                "{\n\t.reg .pred p;\n\t"
                "mbarrier.try_wait.parity.acquire.cta.shared::cta.b64 p, [%1], 0, 0x989680;\n\t"
                "selp.b32 %0, 1, 0, p;\n\t}"
                : "=r"(done) : "r"(mbar_a) : "memory");
        }
    }

    float acc0 = 0.f, acc1 = 0.f, acc2 = 0.f, acc3 = 0.f;
    float acc4 = 0.f, acc5 = 0.f, acc6 = 0.f, acc7 = 0.f;

    #pragma unroll
    for (int s4 = 0; s4 < SAMPLE / 4; ++s4) {
        const uint4 pk = (s4 == 0) ? pk0 : g_pk[s4 * NUM_DEND + d];   // coalesced

        // fp16 group accumulators (4 samples per group; products ~0.2, sums <0.8)
        __half2 s0 = __half2half2(__ushort_as_half((unsigned short)0));
        __half2 s1 = s0, s2 = s0, s3 = s0;

        #pragma unroll
        for (int q = 0; q < 4; ++q) {
            const unsigned u = (q == 0) ? pk.x : (q == 1) ? pk.y : (q == 2) ? pk.z : pk.w;
            const __half2 w2 = __half2half2(__ushort_as_half((unsigned short)u));
            const uint4 raw = *reinterpret_cast<const uint4*>(
                reinterpret_cast<const char*>(xs) + (u >> 16));
            s0 = __hfma2(w2, *reinterpret_cast<const __half2*>(&raw.x), s0);
            s1 = __hfma2(w2, *reinterpret_cast<const __half2*>(&raw.y), s1);
            s2 = __hfma2(w2, *reinterpret_cast<const __half2*>(&raw.z), s2);
            s3 = __hfma2(w2, *reinterpret_cast<const __half2*>(&raw.w), s3);
        }

        // Convert group sums once and fold into fp32 accumulators
        const float2 f0 = __half22float2(s0);
        const float2 f1 = __half22float2(s1);
        const float2 f2 = __half22float2(s2);
        const float2 f3 = __half22float2(s3);
        acc0 += f0.x; acc1 += f0.y;
        acc2 += f1.x; acc3 += f1.y;
        acc4 += f2.x; acc5 += f2.y;
        acc6 += f3.x; acc7 += f3.y;
    }

    float accs[BT] = {acc0, acc1, acc2, acc3, acc4, acc5, acc6, acc7};
    float sv[BT];
    #pragma unroll
    for (int j = 0; j < BT; ++j) {
        float p = accs[j] + bias;
        float a = p >= 0.f ? p : NEG * p;
        dend_out[(size_t)(b0 + j) * NUM_DEND + d] = a;
        sv[j] = a * cwv;
    }

    #pragma unroll
    for (int off = 8; off >= 1; off >>= 1) {
        #pragma unroll
        for (int j = 0; j < BT; ++j)
            sv[j] += __shfl_xor_sync(0xffffffffu, sv[j], off);
    }

    if ((tid & (BRANCH - 1)) == 0) {
        const int n  = d >> 4;
        const float nb = somab[n];
        #pragma unroll
        for (int j = 0; j < BT; ++j) {
            float p = sv[j] + nb;
            soma_out[(size_t)(b0 + j) * SOMA + n] = p >= 0.f ? p : NEG * p;
        }
    }
}

extern "C" void kernel_launch(void* const* d_in, const int* in_sizes, int n_in,
                              void* d_out, int out_size)
{
    const float* x     = (const float*)d_in[0];
    const int*   idx   = (const int*)  d_in[1];
    const float* sw    = (const float*)d_in[2];
    const float* sb    = (const float*)d_in[3];
    const float* cw    = (const float*)d_in[4];
    const float* somab = (const float*)d_in[5];

    float* out      = (float*)d_out;
    float* soma_out = out;                          // [256, 2048]
    float* dend_out = out + (size_t)BATCH * SOMA;   // [256, 32768]

    prep_fused<<<XB + PB, PREP_THREADS>>>(x, idx, sw);

    const size_t smem = XS_BYTES;  // 64 KB dynamic
    cudaFuncSetAttribute(dend_kernel, cudaFuncAttributeMaxDynamicSharedMemorySize, (int)smem);

    cudaLaunchConfig_t cfg = {};
    cfg.gridDim  = dim3(NUM_DEND / DT, BATCH / BT, 1);
    cfg.blockDim = dim3(NTHREADS, 1, 1);
    cfg.dynamicSmemBytes = smem;
    cfg.stream = 0;
    cudaLaunchAttribute attr[1];
    attr[0].id = cudaLaunchAttributeProgrammaticStreamSerialization;
    attr[0].val.programmaticStreamSerializationAllowed = 1;
    cfg.attrs = attr;
    cfg.numAttrs = 1;
    cudaLaunchKernelEx(&cfg, dend_kernel, sb, cw, somab, soma_out, dend_out);
}

// round 12
// speedup vs baseline: 1.0721x; 1.0721x over previous
#include <cuda_runtime.h>
#include <cuda_fp16.h>
#include <cstdint>

#define BATCH      256
#define INPUT_DIM  4096
#define SOMA       2048
#define BRANCH     16
#define NUM_DEND   (SOMA * BRANCH)   // 32768
#define SAMPLE     32
#define NEG        0.1f

#define BT         8                 // batches per block (4x half2 = 16B per x element)
#define NBG        (BATCH / BT)      // 32 batch groups
#define DT         512
#define NTHREADS   512

#define PREP_THREADS 256
#define XB   ((NBG * 2 * INPUT_DIM) / PREP_THREADS)   // 1024 blocks for x prep
#define PB   (NUM_DEND / PREP_THREADS)                // 128 blocks for pack prep

#define XS_BYTES (INPUT_DIM * 16)    // 64 KB

// Scratch (allocation-free rule: __device__ globals)
// pk word layout: [15:0] = w (fp16 bits), [31:16] = ix<<4 (byte offset)
__device__ uint4  g_pk[(SAMPLE/4) * NUM_DEND];     // [s4][d], 4 MB
__device__ uint4  g_xprep[NBG * INPUT_DIM];        // [bg][i]: 8 batches as 4x half2, 2 MB

__device__ __forceinline__ uint32_t smem_u32(const void* p) {
    uint32_t a;
    asm("{ .reg .u64 t; cvta.to.shared.u64 t, %1; cvt.u32.u64 %0, t; }" : "=r"(a) : "l"(p));
    return a;
}

// ---- fused pre-pass: x packing (blocks < XB) + idx/w pack-sort (blocks >= XB) ----
__global__ void prep_fused(const float* __restrict__ x,
                           const int*   __restrict__ idx,
                           const float* __restrict__ sw)
{
    asm volatile("griddepcontrol.launch_dependents;");

    __shared__ unsigned buf[SAMPLE * PREP_THREADS];  // 32 KB (used by pack part)
    const int tid = threadIdx.x;

    if (blockIdx.x < XB) {
        // ---- pack x into batch-interleaved fp16 ----
        int t  = blockIdx.x * PREP_THREADS + tid;     // 0 .. NBG*2*INPUT_DIM-1
        int bg = t / (2 * INPUT_DIM);
        int r  = t - bg * 2 * INPUT_DIM;
        int h  = r / INPUT_DIM;
        int i  = r - h * INPUT_DIM;

        const float* xr = x + ((size_t)bg * BT + h * 4) * INPUT_DIM + i;
        __half2 a = __floats2half2_rn(xr[0],             xr[INPUT_DIM]);
        __half2 b = __floats2half2_rn(xr[2 * INPUT_DIM], xr[3 * INPUT_DIM]);
        uint2 v;
        v.x = *reinterpret_cast<unsigned*>(&a);
        v.y = *reinterpret_cast<unsigned*>(&b);
        reinterpret_cast<uint2*>(g_xprep)[(size_t)(bg * INPUT_DIM + i) * 2 + h] = v;
        return;
    }

    // ---- pack {off16 = ix<<4, w fp16} with FIXED-SLOT bank-class schedule ----
    const int d = (blockIdx.x - XB) * PREP_THREADS + tid;

    const int4*   ir = reinterpret_cast<const int4*>(idx) + (size_t)d * (SAMPLE/4);
    const float4* wr = reinterpret_cast<const float4*>(sw) + (size_t)d * (SAMPLE/4);

    unsigned pkv[SAMPLE];
    #pragma unroll
    for (int s4 = 0; s4 < SAMPLE/4; ++s4) {
        const int4   i4 = ir[s4];
        const float4 w4 = wr[s4];
        #pragma unroll
        for (int q = 0; q < 4; ++q) {
            const int   ix = (q == 0) ? i4.x : (q == 1) ? i4.y : (q == 2) ? i4.z : i4.w;
            const float w  = (q == 0) ? w4.x : (q == 1) ? w4.y : (q == 2) ? w4.z : w4.w;
            pkv[4*s4 + q] = (unsigned)__half_as_ushort(__float2half_rn(w))
                          | ((unsigned)ix << 20);            // (ix<<4) in high 16
        }
    }

    // Pass A: class c (= ix&7 = bits [22:20]) owns slots 4c..4c+3
    unsigned long long fill = 0ull;
    unsigned unplaced = 0u;
    #pragma unroll
    for (int e = 0; e < SAMPLE; ++e) {
        const int c = (int)((pkv[e] >> 20) & 7u);
        const int p = (int)((fill >> (8 * c)) & 0xff);
        if (p < 4) {
            fill += 1ull << (8 * c);
            buf[(4 * c + p) * PREP_THREADS + tid] = pkv[e];
        } else {
            unplaced |= 1u << e;
        }
    }
    // Pass B: overflow fills deficit slots (static pkv indices)
    {
        int cslot = 0;
        #pragma unroll
        for (int e = 0; e < SAMPLE; ++e) {
            if ((unplaced >> e) & 1u) {
                while (((fill >> (8 * cslot)) & 0xffull) >= 4) ++cslot;
                const int p = (int)((fill >> (8 * cslot)) & 0xff);
                fill += 1ull << (8 * cslot);
                buf[(4 * cslot + p) * PREP_THREADS + tid] = pkv[e];
            }
        }
    }

    // Output with per-lane rotation so quarter-warp classes are staggered
    const int rot = 4 * (d & 7);
    #pragma unroll
    for (int s4 = 0; s4 < SAMPLE/4; ++s4) {
        uint4 p;
        p.x = buf[(((4*s4 + 0) + rot) & 31) * PREP_THREADS + tid];
        p.y = buf[(((4*s4 + 1) + rot) & 31) * PREP_THREADS + tid];
        p.z = buf[(((4*s4 + 2) + rot) & 31) * PREP_THREADS + tid];
        p.w = buf[(((4*s4 + 3) + rot) & 31) * PREP_THREADS + tid];
        g_pk[s4 * NUM_DEND + d] = p;
    }
}

// ---- main kernel: 3 CTAs/SM target (regs <= 40) ----
__global__ __launch_bounds__(NTHREADS, 3)
void dend_kernel(const float* __restrict__ sb,
                 const float* __restrict__ cw,
                 const float* __restrict__ somab,
                 float* __restrict__ soma_out,
                 float* __restrict__ dend_out)
{
    extern __shared__ uint4 xs[];   // [INPUT_DIM] = 64 KB
    __shared__ __align__(8) uint64_t mbar;

    const int bg  = blockIdx.y;
    const int b0  = bg * BT;
    const int d0  = blockIdx.x * DT;
    const int tid = threadIdx.x;

    const uint32_t mbar_a = smem_u32(&mbar);
    const uint32_t xs_a   = smem_u32(xs);

    if (tid == 0) {
        asm volatile("mbarrier.init.shared::cta.b64 [%0], 1;" :: "r"(mbar_a) : "memory");
    }
    __syncthreads();

    // PDL: block until prep_fused fully completes (memory visible)
    asm volatile("griddepcontrol.wait;" ::: "memory");

    if (tid == 0) {
        asm volatile("mbarrier.arrive.expect_tx.shared::cta.b64 _, [%0], %1;"
                     :: "r"(mbar_a), "r"((unsigned)XS_BYTES) : "memory");
        asm volatile("cp.async.bulk.shared::cta.global.mbarrier::complete_tx::bytes "
                     "[%0], [%1], %2, [%3];"
                     :: "r"(xs_a), "l"(g_xprep + (size_t)bg * INPUT_DIM),
                        "r"((unsigned)XS_BYTES), "r"(mbar_a) : "memory");
    }

    const int d = d0 + tid;

    // Prefetch first pk while TMA fills smem (bias/cw deferred to save regs)
    const uint4 pk0 = g_pk[d];

    // Wait for bulk copy completion (phase 0)
    {
        unsigned done;
        asm volatile(
            "{\n\t.reg .pred p;\n\t"
            "mbarrier.try_wait.parity.acquire.cta.shared::cta.b64 p, [%1], 0;\n\t"
            "selp.b32 %0, 1, 0, p;\n\t}"
            : "=r"(done) : "r"(mbar_a) : "memory");
        while (!done) {
            asm volatile(
                "{\n\t.reg .pred p;\n\t"
                "mbarrier.try_wait.parity.acquire.cta.shared::cta.b64 p, [%1], 0, 0x989680;\n\t"
                "selp.b32 %0, 1, 0, p;\n\t}"
                : "=r"(done) : "r"(mbar_a) : "memory");
        }
    }

    float acc0 = 0.f, acc1 = 0.f, acc2 = 0.f, acc3 = 0.f;
    float acc4 = 0.f, acc5 = 0.f, acc6 = 0.f, acc7 = 0.f;

    #pragma unroll
    for (int s4 = 0; s4 < SAMPLE / 4; ++s4) {
        const uint4 pk = (s4 == 0) ? pk0 : g_pk[s4 * NUM_DEND + d];   // coalesced

        #pragma unroll
        for (int q = 0; q < 4; ++q) {
            const unsigned u = (q == 0) ? pk.x : (q == 1) ? pk.y : (q == 2) ? pk.z : pk.w;
            // w from low 16 bits (direct F2F, no shift)
            const float w = __half2float(__ushort_as_half((unsigned short)u));
            // byte offset = u >> 16  (pre-scaled ix<<4)
            const uint4 raw = *reinterpret_cast<const uint4*>(
                reinterpret_cast<const char*>(xs) + (u >> 16));
            float2 f0 = __half22float2(*reinterpret_cast<const __half2*>(&raw.x));
            float2 f1 = __half22float2(*reinterpret_cast<const __half2*>(&raw.y));
            float2 f2 = __half22float2(*reinterpret_cast<const __half2*>(&raw.z));
            float2 f3 = __half22float2(*reinterpret_cast<const __half2*>(&raw.w));
            acc0 = fmaf(w, f0.x, acc0); acc1 = fmaf(w, f0.y, acc1);
            acc2 = fmaf(w, f1.x, acc2); acc3 = fmaf(w, f1.y, acc3);
            acc4 = fmaf(w, f2.x, acc4); acc5 = fmaf(w, f2.y, acc5);
            acc6 = fmaf(w, f3.x, acc6); acc7 = fmaf(w, f3.y, acc7);
        }
    }

    const float bias = sb[d];
    const float cwv  = cw[d];   // cable_weights flattened [soma][branch] == index d

    float accs[BT] = {acc0, acc1, acc2, acc3, acc4, acc5, acc6, acc7};
    float sv[BT];
    #pragma unroll
    for (int j = 0; j < BT; ++j) {
        float p = accs[j] + bias;
        float a = p >= 0.f ? p : NEG * p;
        dend_out[(size_t)(b0 + j) * NUM_DEND + d] = a;
        sv[j] = a * cwv;
    }

    #pragma unroll
    for (int off = 8; off >= 1; off >>= 1) {
        #pragma unroll
        for (int j = 0; j < BT; ++j)
            sv[j] += __shfl_xor_sync(0xffffffffu, sv[j], off);
    }

    if ((tid & (BRANCH - 1)) == 0) {
        const int n  = d >> 4;
        const float nb = somab[n];
        #pragma unroll
        for (int j = 0; j < BT; ++j) {
            float p = sv[j] + nb;
            soma_out[(size_t)(b0 + j) * SOMA + n] = p >= 0.f ? p : NEG * p;
        }
    }
}

extern "C" void kernel_launch(void* const* d_in, const int* in_sizes, int n_in,
                              void* d_out, int out_size)
{
    const float* x     = (const float*)d_in[0];
    const int*   idx   = (const int*)  d_in[1];
    const float* sw    = (const float*)d_in[2];
    const float* sb    = (const float*)d_in[3];
    const float* cw    = (const float*)d_in[4];
    const float* somab = (const float*)d_in[5];

    float* out      = (float*)d_out;
    float* soma_out = out;                          // [256, 2048]
    float* dend_out = out + (size_t)BATCH * SOMA;   // [256, 32768]

    prep_fused<<<XB + PB, PREP_THREADS>>>(x, idx, sw);

    const size_t smem = XS_BYTES;  // 64 KB dynamic
    cudaFuncSetAttribute(dend_kernel, cudaFuncAttributeMaxDynamicSharedMemorySize, (int)smem);

    cudaLaunchConfig_t cfg = {};
    cfg.gridDim  = dim3(NUM_DEND / DT, BATCH / BT, 1);
    cfg.blockDim = dim3(NTHREADS, 1, 1);
    cfg.dynamicSmemBytes = smem;
    cfg.stream = 0;
    cudaLaunchAttribute attr[1];
    attr[0].id = cudaLaunchAttributeProgrammaticStreamSerialization;
    attr[0].val.programmaticStreamSerializationAllowed = 1;
    cfg.attrs = attr;
    cfg.numAttrs = 1;
    cudaLaunchKernelEx(&cfg, dend_kernel, sb, cw, somab, soma_out, dend_out);
}

// round 13
// speedup vs baseline: 1.1438x; 1.0668x over previous
#include <cuda_runtime.h>
#include <cuda_fp16.h>
#include <cstdint>

#define BATCH      256
#define INPUT_DIM  4096
#define SOMA       2048
#define BRANCH     16
#define NUM_DEND   (SOMA * BRANCH)   // 32768
#define SAMPLE     32
#define NEG        0.1f

#define BT         8                 // batches per block (4x half2 = 16B per x element)
#define NBG        (BATCH / BT)      // 32 batch groups
#define DT         512
#define NTHREADS   512

#define PREP_THREADS 256
#define XB   ((NBG * 2 * INPUT_DIM) / PREP_THREADS)   // 1024 blocks for x prep
#define PB   (NUM_DEND / PREP_THREADS)                // 128 blocks for pack prep

#define XS_BYTES (INPUT_DIM * 16)    // 64 KB

// Scratch (allocation-free rule: __device__ globals)
// pk word layout: [15:0] = w (fp16 bits), [31:16] = ix<<4 (byte offset)
__device__ uint4  g_pk[(SAMPLE/4) * NUM_DEND];     // [s4][d], 4 MB
__device__ uint4  g_xprep[NBG * INPUT_DIM];        // [bg][i]: 8 batches as 4x half2, 2 MB

__device__ __forceinline__ uint32_t smem_u32(const void* p) {
    uint32_t a;
    asm("{ .reg .u64 t; cvta.to.shared.u64 t, %1; cvt.u32.u64 %0, t; }" : "=r"(a) : "l"(p));
    return a;
}

// ---- fused pre-pass: x packing (blocks < XB) + idx/w pack-sort (blocks >= XB) ----
__global__ void prep_fused(const float* __restrict__ x,
                           const int*   __restrict__ idx,
                           const float* __restrict__ sw)
{
    asm volatile("griddepcontrol.launch_dependents;");

    __shared__ unsigned buf[SAMPLE * PREP_THREADS];  // 32 KB (used by pack part)
    const int tid = threadIdx.x;

    if (blockIdx.x < XB) {
        // ---- pack x into batch-interleaved fp16 ----
        int t  = blockIdx.x * PREP_THREADS + tid;     // 0 .. NBG*2*INPUT_DIM-1
        int bg = t / (2 * INPUT_DIM);
        int r  = t - bg * 2 * INPUT_DIM;
        int h  = r / INPUT_DIM;
        int i  = r - h * INPUT_DIM;

        const float* xr = x + ((size_t)bg * BT + h * 4) * INPUT_DIM + i;
        __half2 a = __floats2half2_rn(xr[0],             xr[INPUT_DIM]);
        __half2 b = __floats2half2_rn(xr[2 * INPUT_DIM], xr[3 * INPUT_DIM]);
        uint2 v;
        v.x = *reinterpret_cast<unsigned*>(&a);
        v.y = *reinterpret_cast<unsigned*>(&b);
        reinterpret_cast<uint2*>(g_xprep)[(size_t)(bg * INPUT_DIM + i) * 2 + h] = v;
        return;
    }

    // ---- pack {off16 = ix<<4, w fp16} with FIXED-SLOT bank-class schedule ----
    const int d = (blockIdx.x - XB) * PREP_THREADS + tid;

    const int4*   ir = reinterpret_cast<const int4*>(idx) + (size_t)d * (SAMPLE/4);
    const float4* wr = reinterpret_cast<const float4*>(sw) + (size_t)d * (SAMPLE/4);

    unsigned pkv[SAMPLE];
    #pragma unroll
    for (int s4 = 0; s4 < SAMPLE/4; ++s4) {
        const int4   i4 = ir[s4];
        const float4 w4 = wr[s4];
        #pragma unroll
        for (int q = 0; q < 4; ++q) {
            const int   ix = (q == 0) ? i4.x : (q == 1) ? i4.y : (q == 2) ? i4.z : i4.w;
            const float w  = (q == 0) ? w4.x : (q == 1) ? w4.y : (q == 2) ? w4.z : w4.w;
            pkv[4*s4 + q] = (unsigned)__half_as_ushort(__float2half_rn(w))
                          | ((unsigned)ix << 20);            // (ix<<4) in high 16
        }
    }

    // Pass A: class c (= ix&7 = bits [22:20]) owns slots 4c..4c+3
    unsigned long long fill = 0ull;
    unsigned unplaced = 0u;
    #pragma unroll
    for (int e = 0; e < SAMPLE; ++e) {
        const int c = (int)((pkv[e] >> 20) & 7u);
        const int p = (int)((fill >> (8 * c)) & 0xff);
        if (p < 4) {
            fill += 1ull << (8 * c);
            buf[(4 * c + p) * PREP_THREADS + tid] = pkv[e];
        } else {
            unplaced |= 1u << e;
        }
    }
    // Pass B: overflow fills deficit slots (static pkv indices)
    {
        int cslot = 0;
        #pragma unroll
        for (int e = 0; e < SAMPLE; ++e) {
            if ((unplaced >> e) & 1u) {
                while (((fill >> (8 * cslot)) & 0xffull) >= 4) ++cslot;
                const int p = (int)((fill >> (8 * cslot)) & 0xff);
                fill += 1ull << (8 * cslot);
                buf[(4 * cslot + p) * PREP_THREADS + tid] = pkv[e];
            }
        }
    }

    // Output with per-lane rotation so quarter-warp classes are staggered
    const int rot = 4 * (d & 7);
    #pragma unroll
    for (int s4 = 0; s4 < SAMPLE/4; ++s4) {
        uint4 p;
        p.x = buf[(((4*s4 + 0) + rot) & 31) * PREP_THREADS + tid];
        p.y = buf[(((4*s4 + 1) + rot) & 31) * PREP_THREADS + tid];
        p.z = buf[(((4*s4 + 2) + rot) & 31) * PREP_THREADS + tid];
        p.w = buf[(((4*s4 + 3) + rot) & 31) * PREP_THREADS + tid];
        g_pk[s4 * NUM_DEND + d] = p;
    }
}

// ---- main kernel: 3 CTAs/SM (regs <= 40) ----
__global__ __launch_bounds__(NTHREADS, 3)
void dend_kernel(const float* __restrict__ sb,
                 const float* __restrict__ cw,
                 const float* __restrict__ somab,
                 float* __restrict__ soma_out,
                 float* __restrict__ dend_out)
{
    extern __shared__ uint4 xs[];   // [INPUT_DIM] = 64 KB
    __shared__ __align__(8) uint64_t mbar;

    const int bg  = blockIdx.y;
    const int b0  = bg * BT;
    const int d0  = blockIdx.x * DT;
    const int tid = threadIdx.x;

    const uint32_t mbar_a = smem_u32(&mbar);
    const uint32_t xs_a   = smem_u32(xs);

    if (tid == 0) {
        asm volatile("mbarrier.init.shared::cta.b64 [%0], 1;" :: "r"(mbar_a) : "memory");
    }
    __syncthreads();

    // PDL: block until prep_fused fully completes (memory visible)
    asm volatile("griddepcontrol.wait;" ::: "memory");

    if (tid == 0) {
        asm volatile("mbarrier.arrive.expect_tx.shared::cta.b64 _, [%0], %1;"
                     :: "r"(mbar_a), "r"((unsigned)XS_BYTES) : "memory");
        asm volatile("cp.async.bulk.shared::cta.global.mbarrier::complete_tx::bytes "
                     "[%0], [%1], %2, [%3];"
                     :: "r"(xs_a), "l"(g_xprep + (size_t)bg * INPUT_DIM),
                        "r"((unsigned)XS_BYTES), "r"(mbar_a) : "memory");
    }

    const int d = d0 + tid;

    // Prefetch first pk while TMA fills smem
    const uint4 pk0 = g_pk[d];

    // Wait for bulk copy completion (phase 0)
    {
        unsigned done;
        asm volatile(
            "{\n\t.reg .pred p;\n\t"
            "mbarrier.try_wait.parity.acquire.cta.shared::cta.b64 p, [%1], 0;\n\t"
            "selp.b32 %0, 1, 0, p;\n\t}"
            : "=r"(done) : "r"(mbar_a) : "memory");
        while (!done) {
            asm volatile(
                "{\n\t.reg .pred p;\n\t"
                "mbarrier.try_wait.parity.acquire.cta.shared::cta.b64 p, [%1], 0, 0x989680;\n\t"
                "selp.b32 %0, 1, 0, p;\n\t}"
                : "=r"(done) : "r"(mbar_a) : "memory");
        }
    }

    float acc0 = 0.f, acc1 = 0.f, acc2 = 0.f, acc3 = 0.f;
    float acc4 = 0.f, acc5 = 0.f, acc6 = 0.f, acc7 = 0.f;

    #pragma unroll
    for (int s4 = 0; s4 < SAMPLE / 4; ++s4) {
        const uint4 pk = (s4 == 0) ? pk0 : g_pk[s4 * NUM_DEND + d];   // coalesced

        #pragma unroll
        for (int q = 0; q < 4; ++q) {
            const unsigned u = (q == 0) ? pk.x : (q == 1) ? pk.y : (q == 2) ? pk.z : pk.w;
            const float w = __half2float(__ushort_as_half((unsigned short)u));
            const uint4 raw = *reinterpret_cast<const uint4*>(
                reinterpret_cast<const char*>(xs) + (u >> 16));
            float2 f0 = __half22float2(*reinterpret_cast<const __half2*>(&raw.x));
            float2 f1 = __half22float2(*reinterpret_cast<const __half2*>(&raw.y));
            float2 f2 = __half22float2(*reinterpret_cast<const __half2*>(&raw.z));
            float2 f3 = __half22float2(*reinterpret_cast<const __half2*>(&raw.w));
            acc0 = fmaf(w, f0.x, acc0); acc1 = fmaf(w, f0.y, acc1);
            acc2 = fmaf(w, f1.x, acc2); acc3 = fmaf(w, f1.y, acc3);
            acc4 = fmaf(w, f2.x, acc4); acc5 = fmaf(w, f2.y, acc5);
            acc6 = fmaf(w, f3.x, acc6); acc7 = fmaf(w, f3.y, acc7);
        }
    }

    const float bias = sb[d];
    const float cwv  = cw[d];   // cable_weights flattened [soma][branch] == index d

    float sv[BT];
    {
        float accs[BT] = {acc0, acc1, acc2, acc3, acc4, acc5, acc6, acc7};
        #pragma unroll
        for (int j = 0; j < BT; ++j) {
            float p = accs[j] + bias;
            float a = p >= 0.f ? p : NEG * p;
            dend_out[(size_t)(b0 + j) * NUM_DEND + d] = a;
            sv[j] = a * cwv;
        }
    }

    // Value-folding butterfly over the 16-lane segment:
    // each xor stage halves the j-set; 8 SHFL + 8 FADD total.
    const int lid = tid & 31;

    // Stage A (xor 8): keep 4 values; lanes with bit3 own j = k+4
    float a4[4];
    {
        const bool hi = (lid & 8) != 0;
        #pragma unroll
        for (int k = 0; k < 4; ++k) {
            float give = hi ? sv[k] : sv[k + 4];
            float recv = __shfl_xor_sync(0xffffffffu, give, 8);
            a4[k] = (hi ? sv[k + 4] : sv[k]) + recv;
        }
    }
    // Stage B (xor 4): keep 2; bit2 adds offset 2
    float b2[2];
    {
        const bool hi = (lid & 4) != 0;
        #pragma unroll
        for (int k = 0; k < 2; ++k) {
            float give = hi ? a4[k] : a4[k + 2];
            float recv = __shfl_xor_sync(0xffffffffu, give, 4);
            b2[k] = (hi ? a4[k + 2] : a4[k]) + recv;
        }
    }
    // Stage C (xor 2): keep 1; bit1 adds offset 1
    float c1;
    {
        const bool hi = (lid & 2) != 0;
        float give = hi ? b2[0] : b2[1];
        float recv = __shfl_xor_sync(0xffffffffu, give, 2);
        c1 = (hi ? b2[1] : b2[0]) + recv;
    }
    // Stage D (xor 1): complete the 16-lane sum
    c1 += __shfl_xor_sync(0xffffffffu, c1, 1);

    // Lane holds soma sum for batch j = 4*b3 + 2*b2 + b1; b0==0 lanes write
    if ((lid & 1) == 0) {
        const int j = ((lid >> 1) & 1) | ((lid >> 1) & 2) | ((lid >> 1) & 4);
        const int n = d >> 4;               // same soma for the whole segment
        float p = c1 + somab[n];
        soma_out[(size_t)(b0 + j) * SOMA + n] = p >= 0.f ? p : NEG * p;
    }
}

extern "C" void kernel_launch(void* const* d_in, const int* in_sizes, int n_in,
                              void* d_out, int out_size)
{
    const float* x     = (const float*)d_in[0];
    const int*   idx   = (const int*)  d_in[1];
    const float* sw    = (const float*)d_in[2];
    const float* sb    = (const float*)d_in[3];
    const float* cw    = (const float*)d_in[4];
    const float* somab = (const float*)d_in[5];

    float* out      = (float*)d_out;
    float* soma_out = out;                          // [256, 2048]
    float* dend_out = out + (size_t)BATCH * SOMA;   // [256, 32768]

    prep_fused<<<XB + PB, PREP_THREADS>>>(x, idx, sw);

    const size_t smem = XS_BYTES;  // 64 KB dynamic
    cudaFuncSetAttribute(dend_kernel, cudaFuncAttributeMaxDynamicSharedMemorySize, (int)smem);

    cudaLaunchConfig_t cfg = {};
    cfg.gridDim  = dim3(NUM_DEND / DT, BATCH / BT, 1);
    cfg.blockDim = dim3(NTHREADS, 1, 1);
    cfg.dynamicSmemBytes = smem;
    cfg.stream = 0;
    cudaLaunchAttribute attr[1];
    attr[0].id = cudaLaunchAttributeProgrammaticStreamSerialization;
    attr[0].val.programmaticStreamSerializationAllowed = 1;
    cfg.attrs = attr;
    cfg.numAttrs = 1;
    cudaLaunchKernelEx(&cfg, dend_kernel, sb, cw, somab, soma_out, dend_out);
}